// round 1
// baseline (speedup 1.0000x reference)
#include <cuda_runtime.h>
#include <cstdint>
#include <cstddef>

#define MAXN 50000
#define MAXE 400000

// ---------------- persistent device scratch (no allocations allowed) ----------------
__device__ float d_t0[(size_t)MAXN * 256];
__device__ float d_w0[(size_t)MAXN * 256];
__device__ float d_t1[(size_t)MAXN * 256];
__device__ float d_w1[(size_t)MAXN * 256];
__device__ float d_hs[4 * (size_t)MAXN * 256];   // per-relation H_src / hn buffers
__device__ float d_el[4 * (size_t)MAXN * 4];
__device__ float d_er[4 * (size_t)MAXN * 4];
__device__ float d_alv[4 * 64 * 4];
__device__ float d_arv[4 * 64 * 4];
__device__ int   d_cnt[4 * MAXN];
__device__ int   d_rpv[4 * (MAXN + 1)];
__device__ int   d_colv[4 * MAXE];

// ---------------- GEMM: C[M,N] = A[M,K] @ B[K,N] (+bias)(+=C)(relu) ----------------
// BM=BN=64, BK=16, 256 threads, 4x4 per-thread tile.
#define GF_ACC 1
#define GF_RELU 2

__global__ void gemm_kernel(const float* __restrict__ A, const float* __restrict__ B,
                            float* __restrict__ C, const float* __restrict__ bias,
                            int M, int N, int K, int flags)
{
    __shared__ float As[16][68];   // padded to reduce STS conflicts, keeps 16B alignment
    __shared__ float Bs[16][64];
    const int tid = threadIdx.x;
    const int tx = tid & 15, ty = tid >> 4;
    const int m0 = blockIdx.y * 64, n0 = blockIdx.x * 64;

    float acc[4][4] = {};

    for (int k0 = 0; k0 < K; k0 += 16) {
#pragma unroll
        for (int i = 0; i < 4; i++) {
            int lin = tid + i * 256;          // 1024 elems: 64 rows x 16 k
            int r = lin >> 4, c = lin & 15;
            int gm = m0 + r, gk = k0 + c;
            As[c][r] = (gm < M && gk < K) ? A[(size_t)gm * K + gk] : 0.f;
        }
#pragma unroll
        for (int i = 0; i < 4; i++) {
            int lin = tid + i * 256;          // 16 rows x 64 n
            int r = lin >> 6, c = lin & 63;
            int gk = k0 + r, gn = n0 + c;
            Bs[r][c] = (gk < K && gn < N) ? B[(size_t)gk * N + gn] : 0.f;
        }
        __syncthreads();
#pragma unroll
        for (int k = 0; k < 16; k++) {
            float4 av = *(const float4*)&As[k][ty * 4];
            float4 bv = *(const float4*)&Bs[k][tx * 4];
            float a[4] = {av.x, av.y, av.z, av.w};
            float b[4] = {bv.x, bv.y, bv.z, bv.w};
#pragma unroll
            for (int i = 0; i < 4; i++)
#pragma unroll
                for (int j = 0; j < 4; j++)
                    acc[i][j] = fmaf(a[i], b[j], acc[i][j]);
        }
        __syncthreads();
    }

#pragma unroll
    for (int i = 0; i < 4; i++) {
        int gm = m0 + ty * 4 + i;
        if (gm >= M) continue;
#pragma unroll
        for (int j = 0; j < 4; j++) {
            int gn = n0 + tx * 4 + j;
            if (gn >= N) continue;
            float v = acc[i][j];
            if (bias) v += bias[gn];
            size_t off = (size_t)gm * N + gn;
            if (flags & GF_ACC) v += C[off];
            if (flags & GF_RELU) v = fmaxf(v, 0.f);
            C[off] = v;
        }
    }
}

// ------------- fold attention vectors into K-side: v[k,h] = sum_d W[k, h*64+d]*a[h,d] -------------
__global__ void attnvec_kernel(const float* __restrict__ W, const float* __restrict__ al,
                               const float* __restrict__ ar,
                               float* __restrict__ alv, float* __restrict__ arv)
{
    int idx = blockIdx.x * 256 + threadIdx.x;      // 2048 total
    if (idx >= 2048) return;
    int type = idx >> 10;
    int rem = idx & 1023;
    int r = rem >> 8;
    int k = (rem >> 2) & 63;
    int h = rem & 3;
    const float* av = type ? ar : al;
    float s = 0.f;
#pragma unroll 16
    for (int d = 0; d < 64; d++)
        s += W[(size_t)r * 16384 + (size_t)k * 256 + h * 64 + d] * av[r * 256 + h * 64 + d];
    (type ? arv : alv)[r * 256 + k * 4 + h] = s;
}

// ------------- el/er projection: out[i,4] = X[i,0:64] @ V[64,4] -------------
__global__ void vecproj_kernel(const float* __restrict__ X, const float* __restrict__ V,
                               float* __restrict__ out, int n)
{
    __shared__ float sv[256];
    if (threadIdx.x < 256) sv[threadIdx.x] = V[threadIdx.x];
    __syncthreads();
    int i = blockIdx.x * blockDim.x + threadIdx.x;
    if (i >= n) return;
    const float* x = X + (size_t)i * 64;
    float a0 = 0, a1 = 0, a2 = 0, a3 = 0;
#pragma unroll 16
    for (int k = 0; k < 64; k++) {
        float xv = __ldg(&x[k]);
        a0 += xv * sv[k * 4 + 0];
        a1 += xv * sv[k * 4 + 1];
        a2 += xv * sv[k * 4 + 2];
        a3 += xv * sv[k * 4 + 3];
    }
    float4* o = (float4*)(out + (size_t)i * 4);
    *o = make_float4(a0, a1, a2, a3);
}

// ---------------- CSR build ----------------
__global__ void hist_kernel(const int* __restrict__ edges, int* __restrict__ cnt, int E, int n)
{
    for (int idx = blockIdx.x * blockDim.x + threadIdx.x; idx < 4 * E; idx += gridDim.x * blockDim.x) {
        int r = idx / E, i = idx - r * E;
        int dst = edges[(size_t)(2 * r + 1) * E + i];
        atomicAdd(&cnt[r * n + dst], 1);
    }
}

__global__ void scan_kernel(const int* __restrict__ cnt, int* __restrict__ rp, int n)
{
    int r = blockIdx.x;
    int t = threadIdx.x;                      // 1024 threads
    int C = (n + 1023) / 1024;
    __shared__ int sums[1024];
    int base = t * C;
    int loc = 0;
    for (int i = 0; i < C; i++) {
        int idx = base + i;
        if (idx < n) loc += cnt[r * n + idx];
    }
    sums[t] = loc;
    __syncthreads();
    for (int off = 1; off < 1024; off <<= 1) {
        int v = (t >= off) ? sums[t - off] : 0;
        __syncthreads();
        sums[t] += v;
        __syncthreads();
    }
    int run = (t == 0) ? 0 : sums[t - 1];
    for (int i = 0; i < C; i++) {
        int idx = base + i;
        if (idx < n) {
            rp[(size_t)r * (n + 1) + idx] = run;
            run += cnt[r * n + idx];
        }
    }
    if (t == 1023) rp[(size_t)r * (n + 1) + n] = sums[1023];
}

__global__ void scatter_kernel(const int* __restrict__ edges, int* __restrict__ cnt,
                               const int* __restrict__ rp, int* __restrict__ col, int E, int n)
{
    for (int idx = blockIdx.x * blockDim.x + threadIdx.x; idx < 4 * E; idx += gridDim.x * blockDim.x) {
        int r = idx / E, i = idx - r * E;
        int src = edges[(size_t)(2 * r) * E + i];
        int dst = edges[(size_t)(2 * r + 1) * E + i];
        int pos = rp[(size_t)r * (n + 1) + dst] + atomicAdd(&cnt[r * n + dst], 1);
        col[(size_t)r * E + pos] = src;
    }
}

// ---------------- GAT aggregation: warp per dst, two relations fused ----------------
__device__ __forceinline__ float lrelu(float x) { return x > 0.f ? x : 0.2f * x; }

__global__ void gat_agg_kernel(float* __restrict__ out,
    const float* __restrict__ Ha, const float* __restrict__ ela, const float* __restrict__ era,
    const int* __restrict__ rpa, const int* __restrict__ cola,
    const float* __restrict__ Hb, const float* __restrict__ elb, const float* __restrict__ erb,
    const int* __restrict__ rpb, const int* __restrict__ colb,
    const float* __restrict__ ba, const float* __restrict__ bb, int n)
{
    int w = (blockIdx.x * blockDim.x + threadIdx.x) >> 5;
    int lane = threadIdx.x & 31;
    if (w >= n) return;

    float acc[8] = {0, 0, 0, 0, 0, 0, 0, 0};

#pragma unroll
    for (int rel = 0; rel < 2; rel++) {
        const float* H  = rel ? Hb : Ha;
        const float* el = rel ? elb : ela;
        const float* er = rel ? erb : era;
        const int* rp   = rel ? rpb : rpa;
        const int* col  = rel ? colb : cola;

        int s0 = rp[w], s1 = rp[w + 1];
        if (s1 <= s0) continue;

        float4 e4 = *(const float4*)(er + (size_t)w * 4);
        float er0 = e4.x, er1 = e4.y, er2 = e4.z, er3 = e4.w;

        // pass 1: per-head max
        float m0 = -1e30f, m1 = -1e30f, m2 = -1e30f, m3 = -1e30f;
        for (int e = s0 + lane; e < s1; e += 32) {
            int s = col[e];
            float4 l4 = *(const float4*)(el + (size_t)s * 4);
            m0 = fmaxf(m0, lrelu(l4.x + er0));
            m1 = fmaxf(m1, lrelu(l4.y + er1));
            m2 = fmaxf(m2, lrelu(l4.z + er2));
            m3 = fmaxf(m3, lrelu(l4.w + er3));
        }
#pragma unroll
        for (int o = 16; o; o >>= 1) {
            m0 = fmaxf(m0, __shfl_xor_sync(0xffffffffu, m0, o));
            m1 = fmaxf(m1, __shfl_xor_sync(0xffffffffu, m1, o));
            m2 = fmaxf(m2, __shfl_xor_sync(0xffffffffu, m2, o));
            m3 = fmaxf(m3, __shfl_xor_sync(0xffffffffu, m3, o));
        }
        // pass 2: per-head sum of exp
        float z0 = 0, z1 = 0, z2 = 0, z3 = 0;
        for (int e = s0 + lane; e < s1; e += 32) {
            int s = col[e];
            float4 l4 = *(const float4*)(el + (size_t)s * 4);
            z0 += __expf(lrelu(l4.x + er0) - m0);
            z1 += __expf(lrelu(l4.y + er1) - m1);
            z2 += __expf(lrelu(l4.z + er2) - m2);
            z3 += __expf(lrelu(l4.w + er3) - m3);
        }
#pragma unroll
        for (int o = 16; o; o >>= 1) {
            z0 += __shfl_xor_sync(0xffffffffu, z0, o);
            z1 += __shfl_xor_sync(0xffffffffu, z1, o);
            z2 += __shfl_xor_sync(0xffffffffu, z2, o);
            z3 += __shfl_xor_sync(0xffffffffu, z3, o);
        }
        float i0 = 1.f / z0, i1 = 1.f / z1, i2 = 1.f / z2, i3 = 1.f / z3;

        // pass 3: weighted accumulate (all lanes walk edges together; lane owns 8 channels)
        for (int e = s0; e < s1; e++) {
            int s = col[e];
            float4 l4 = *(const float4*)(el + (size_t)s * 4);
            float a0 = __expf(lrelu(l4.x + er0) - m0) * i0;
            float a1 = __expf(lrelu(l4.y + er1) - m1) * i1;
            float a2 = __expf(lrelu(l4.z + er2) - m2) * i2;
            float a3 = __expf(lrelu(l4.w + er3) - m3) * i3;
            const float* hp = H + (size_t)s * 256;
            acc[0] = fmaf(a0, hp[lane +   0], acc[0]);
            acc[1] = fmaf(a0, hp[lane +  32], acc[1]);
            acc[2] = fmaf(a1, hp[lane +  64], acc[2]);
            acc[3] = fmaf(a1, hp[lane +  96], acc[3]);
            acc[4] = fmaf(a2, hp[lane + 128], acc[4]);
            acc[5] = fmaf(a2, hp[lane + 160], acc[5]);
            acc[6] = fmaf(a3, hp[lane + 192], acc[6]);
            acc[7] = fmaf(a3, hp[lane + 224], acc[7]);
        }
    }

    float* op = out + (size_t)w * 256;
#pragma unroll
    for (int j = 0; j < 8; j++) {
        int c = lane + 32 * j;
        op[c] = fmaxf(0.f, 0.5f * acc[j] + 0.5f * (ba[c] + bb[c]));
    }
}

// ---------------- SAGE mean aggregation (width 256), warp per dst ----------------
__global__ void sage_mean_kernel(float* __restrict__ out, const float* __restrict__ X,
                                 const int* __restrict__ rp, const int* __restrict__ col, int n)
{
    int w = (blockIdx.x * blockDim.x + threadIdx.x) >> 5;
    int lane = threadIdx.x & 31;
    if (w >= n) return;
    int s0 = rp[w], s1 = rp[w + 1];
    float acc[8] = {0, 0, 0, 0, 0, 0, 0, 0};
    for (int e = s0; e < s1; e++) {
        int s = col[e];
        const float* xp = X + (size_t)s * 256;
#pragma unroll
        for (int j = 0; j < 8; j++) acc[j] += xp[lane + 32 * j];
    }
    float inv = 1.f / fmaxf((float)(s1 - s0), 1.f);
    float* op = out + (size_t)w * 256;
#pragma unroll
    for (int j = 0; j < 8; j++) op[lane + 32 * j] = acc[j] * inv;
}

// ---------------- final SAGE (output dim 2), warp per row ----------------
__global__ void sage2_kernel(float* __restrict__ out, const float* __restrict__ Xd,
                             const float* __restrict__ hA, const float* __restrict__ hB,
                             const float* __restrict__ WsA, const float* __restrict__ WsB,
                             const float* __restrict__ WnA, const float* __restrict__ WnB,
                             const float* __restrict__ bA, const float* __restrict__ bB, int n)
{
    __shared__ float sw[3][512];
    for (int i = threadIdx.x; i < 512; i += blockDim.x) {
        sw[0][i] = WsA[i] + WsB[i];
        sw[1][i] = WnA[i];
        sw[2][i] = WnB[i];
    }
    __syncthreads();
    int w = (blockIdx.x * blockDim.x + threadIdx.x) >> 5;
    int lane = threadIdx.x & 31;
    if (w >= n) return;
    float a0 = 0, a1 = 0;
    for (int k = lane; k < 256; k += 32) {
        float x = Xd[(size_t)w * 256 + k];
        a0 += x * sw[0][2 * k];     a1 += x * sw[0][2 * k + 1];
        float u = hA[(size_t)w * 256 + k];
        a0 += u * sw[1][2 * k];     a1 += u * sw[1][2 * k + 1];
        float v = hB[(size_t)w * 256 + k];
        a0 += v * sw[2][2 * k];     a1 += v * sw[2][2 * k + 1];
    }
#pragma unroll
    for (int o = 16; o; o >>= 1) {
        a0 += __shfl_xor_sync(0xffffffffu, a0, o);
        a1 += __shfl_xor_sync(0xffffffffu, a1, o);
    }
    if (lane == 0) {
        out[(size_t)w * 2 + 0] = a0 + bA[0] + bB[0];
        out[(size_t)w * 2 + 1] = a1 + bA[1] + bB[1];
    }
}

// ---------------- host helpers ----------------
static void gemm(const float* A, const float* B, float* C, const float* bias,
                 int M, int N, int K, int flags)
{
    dim3 g((N + 63) / 64, (M + 63) / 64);
    gemm_kernel<<<g, 256>>>(A, B, C, bias, M, N, K, flags);
}

static void gat_layer(const float* gW, const float* gal, const float* gar, const float* gb,
                      const float* Xt, const float* Xw, float* Ot, float* Ow,
                      float* hs, float* el, float* er, float* alv, float* arv,
                      const int* rp, const int* col, int NT, int NW, int E)
{
    const size_t HOF = (size_t)MAXN * 256;
    const size_t EO4 = (size_t)MAXN * 4;
    attnvec_kernel<<<8, 256>>>(gW, gal, gar, alv, arv);
    for (int r = 0; r < 4; r++) {
        const float* Xs = (r & 1) ? Xt : Xw;
        const float* Xd = (r & 1) ? Xw : Xt;
        int Ns = (r & 1) ? NT : NW;
        int Nd = (r & 1) ? NW : NT;
        gemm(Xs, gW + (size_t)r * 64 * 256, hs + (size_t)r * HOF, nullptr, Ns, 256, 64, 0);
        vecproj_kernel<<<(Ns + 255) / 256, 256>>>(Xs, alv + r * 256, el + (size_t)r * EO4, Ns);
        vecproj_kernel<<<(Nd + 255) / 256, 256>>>(Xd, arv + r * 256, er + (size_t)r * EO4, Nd);
    }
    gat_agg_kernel<<<(NT + 7) / 8, 256>>>(Ot,
        hs + 0 * HOF, el + 0 * EO4, er + 0 * EO4, rp + 0 * (MAXN + 1), col + 0 * (size_t)E,
        hs + 2 * HOF, el + 2 * EO4, er + 2 * EO4, rp + 2 * (MAXN + 1), col + 2 * (size_t)E,
        gb + 0 * 256, gb + 2 * 256, NT);
    gat_agg_kernel<<<(NW + 7) / 8, 256>>>(Ow,
        hs + 1 * HOF, el + 1 * EO4, er + 1 * EO4, rp + 1 * (MAXN + 1), col + 1 * (size_t)E,
        hs + 3 * HOF, el + 3 * EO4, er + 3 * EO4, rp + 3 * (MAXN + 1), col + 3 * (size_t)E,
        gb + 1 * 256, gb + 3 * 256, NW);
}

static void sage_hn(const float* Xt, const float* Xw, float* hs,
                    const int* rp, const int* col, int NT, int NW, int E)
{
    const size_t HOF = (size_t)MAXN * 256;
    sage_mean_kernel<<<(NT + 7) / 8, 256>>>(hs + 0 * HOF, Xw, rp + 0 * (MAXN + 1), col + 0 * (size_t)E, NT);
    sage_mean_kernel<<<(NW + 7) / 8, 256>>>(hs + 1 * HOF, Xt, rp + 1 * (MAXN + 1), col + 1 * (size_t)E, NW);
    sage_mean_kernel<<<(NT + 7) / 8, 256>>>(hs + 2 * HOF, Xw, rp + 2 * (MAXN + 1), col + 2 * (size_t)E, NT);
    sage_mean_kernel<<<(NW + 7) / 8, 256>>>(hs + 3 * HOF, Xt, rp + 3 * (MAXN + 1), col + 3 * (size_t)E, NW);
}

extern "C" void kernel_launch(void* const* d_in, const int* in_sizes, int n_in,
                              void* d_out, int out_size)
{
    const float* tx_feat  = (const float*)d_in[0];
    const float* w_feat   = (const float*)d_in[1];
    const int*   edges    = (const int*)d_in[2];
    const float* tx_W     = (const float*)d_in[3];
    const float* tx_b     = (const float*)d_in[4];
    const float* w_W      = (const float*)d_in[5];
    const float* w_b      = (const float*)d_in[6];
    const float* gat1_W   = (const float*)d_in[7];
    const float* gat1_al  = (const float*)d_in[8];
    const float* gat1_ar  = (const float*)d_in[9];
    const float* gat1_b   = (const float*)d_in[10];
    const float* sage1_Ws = (const float*)d_in[11];
    const float* sage1_Wn = (const float*)d_in[12];
    const float* sage1_b  = (const float*)d_in[13];
    const float* gat2_W   = (const float*)d_in[14];
    const float* gat2_al  = (const float*)d_in[15];
    const float* gat2_ar  = (const float*)d_in[16];
    const float* gat2_b   = (const float*)d_in[17];
    const float* sage2_Ws = (const float*)d_in[18];
    const float* sage2_Wn = (const float*)d_in[19];
    const float* sage2_b  = (const float*)d_in[20];

    int NT = in_sizes[0] / 166;
    int NW = in_sizes[1] / 56;
    int E  = in_sizes[2] / 8;
    if (NT > MAXN) NT = MAXN;
    if (NW > MAXN) NW = MAXN;
    if (E > MAXE) E = MAXE;

    float *t0, *w0, *t1, *w1, *hs, *el, *er, *alv, *arv;
    int *cnt, *rp, *col;
    cudaGetSymbolAddress((void**)&t0, d_t0);
    cudaGetSymbolAddress((void**)&w0, d_w0);
    cudaGetSymbolAddress((void**)&t1, d_t1);
    cudaGetSymbolAddress((void**)&w1, d_w1);
    cudaGetSymbolAddress((void**)&hs, d_hs);
    cudaGetSymbolAddress((void**)&el, d_el);
    cudaGetSymbolAddress((void**)&er, d_er);
    cudaGetSymbolAddress((void**)&alv, d_alv);
    cudaGetSymbolAddress((void**)&arv, d_arv);
    cudaGetSymbolAddress((void**)&cnt, d_cnt);
    cudaGetSymbolAddress((void**)&rp, d_rpv);
    cudaGetSymbolAddress((void**)&col, d_colv);

    const size_t HOF = (size_t)MAXN * 256;
    float* fout = (float*)d_out;

    // ---- CSR build (per relation, dst-sorted) ----
    cudaMemsetAsync(cnt, 0, 4 * (size_t)MAXN * sizeof(int));
    hist_kernel<<<(4 * E + 255) / 256, 256>>>(edges, cnt, E, NT);
    scan_kernel<<<4, 1024>>>(cnt, rp, NT);
    cudaMemsetAsync(cnt, 0, 4 * (size_t)MAXN * sizeof(int));
    scatter_kernel<<<(4 * E + 255) / 256, 256>>>(edges, cnt, rp, col, E, NT);

    // ---- S0: input projections (relu) -> width 64 ----
    gemm(tx_feat, tx_W, t0, tx_b, NT, 64, 166, GF_RELU);
    gemm(w_feat,  w_W,  w0, w_b,  NW, 64, 56,  GF_RELU);

    // ---- S1: hetero GAT1 (64 -> 256, relu fused) ----
    gat_layer(gat1_W, gat1_al, gat1_ar, gat1_b, t0, w0, t1, w1,
              hs, el, er, alv, arv, rp, col, NT, NW, E);

    // ---- S2: hetero SAGE1 (256 -> 64, relu) ----
    sage_hn(t1, w1, hs, rp, col, NT, NW, E);
    gemm(t1, sage1_Ws + 0 * 256 * 64, t0, sage1_b + 0 * 64, NT, 64, 256, 0);
    gemm(t1, sage1_Ws + 2 * 256 * 64, t0, sage1_b + 2 * 64, NT, 64, 256, GF_ACC);
    gemm(hs + 0 * HOF, sage1_Wn + 0 * 256 * 64, t0, nullptr, NT, 64, 256, GF_ACC);
    gemm(hs + 2 * HOF, sage1_Wn + 2 * 256 * 64, t0, nullptr, NT, 64, 256, GF_ACC | GF_RELU);
    gemm(w1, sage1_Ws + 1 * 256 * 64, w0, sage1_b + 1 * 64, NW, 64, 256, 0);
    gemm(w1, sage1_Ws + 3 * 256 * 64, w0, sage1_b + 3 * 64, NW, 64, 256, GF_ACC);
    gemm(hs + 1 * HOF, sage1_Wn + 1 * 256 * 64, w0, nullptr, NW, 64, 256, GF_ACC);
    gemm(hs + 3 * HOF, sage1_Wn + 3 * 256 * 64, w0, nullptr, NW, 64, 256, GF_ACC | GF_RELU);

    // ---- S3: hetero GAT2 (64 -> 256, relu fused) ----
    gat_layer(gat2_W, gat2_al, gat2_ar, gat2_b, t0, w0, t1, w1,
              hs, el, er, alv, arv, rp, col, NT, NW, E);

    // ---- S4: hetero SAGE2 (256 -> 2), no relu ----
    sage_hn(t1, w1, hs, rp, col, NT, NW, E);
    sage2_kernel<<<(NT + 7) / 8, 256>>>(fout, t1, hs + 0 * HOF, hs + 2 * HOF,
        sage2_Ws + 0 * 512, sage2_Ws + 2 * 512, sage2_Wn + 0 * 512, sage2_Wn + 2 * 512,
        sage2_b + 0, sage2_b + 4, NT);
    sage2_kernel<<<(NW + 7) / 8, 256>>>(fout + (size_t)NT * 2, w1, hs + 1 * HOF, hs + 3 * HOF,
        sage2_Ws + 1 * 512, sage2_Ws + 3 * 512, sage2_Wn + 1 * 512, sage2_Wn + 3 * 512,
        sage2_b + 2, sage2_b + 6, NW);
}

// round 2
// speedup vs baseline: 1.3455x; 1.3455x over previous
#include <cuda_runtime.h>
#include <cstdint>
#include <cstddef>

#define MAXN 50000
#define MAXE 400000

// ---------------- persistent device scratch (no allocations allowed) ----------------
__device__ float d_t0[(size_t)MAXN * 256];
__device__ float d_w0[(size_t)MAXN * 256];
__device__ float d_t1[(size_t)MAXN * 256];
__device__ float d_w1[(size_t)MAXN * 256];
__device__ float d_hs[4 * (size_t)MAXN * 256];   // per-relation H_src / hn buffers
__device__ float d_el[4 * (size_t)MAXN * 4];
__device__ float d_er[4 * (size_t)MAXN * 4];
__device__ float d_alv[4 * 64 * 4];
__device__ float d_arv[4 * 64 * 4];
__device__ float d_wsum[2 * 256 * 64];
__device__ float d_bsum[128];
__device__ int   d_cnt[4 * MAXN];
__device__ int   d_rpv[4 * (MAXN + 1)];
__device__ int   d_colv[4 * MAXE];

// ---------------- multi-segment GEMM: C[M,N] = sum_s A_s[M,K] @ B_s[K,N] (+bias)(relu) ----
// BM=128, BN=64, BK=16, 256 threads, 8x4 per-thread tile, register-staged prefetch.
struct GSeg { const float* A; const float* B; };

template<bool VEC>
__launch_bounds__(256, 2)
__global__ void gemm_tile_kernel(GSeg s0, GSeg s1, GSeg s2, int nseg,
                                 float* __restrict__ C, const float* __restrict__ bias,
                                 int M, int N, int K, int relu)
{
    __shared__ float As[16][132];
    __shared__ float Bs[16][68];
    const int tid = threadIdx.x;
    const int tx = tid & 15, ty = tid >> 4;
    const int m0 = blockIdx.y * 128, n0 = blockIdx.x * 64;

    float acc[8][4] = {};

    for (int seg = 0; seg < nseg; seg++) {
        const float* __restrict__ A = (seg == 0) ? s0.A : (seg == 1) ? s1.A : s2.A;
        const float* __restrict__ B = (seg == 0) ? s0.B : (seg == 1) ? s1.B : s2.B;

        float4 ra[2];
        float  a_s[8];
        float4 rb;

        // prologue: stage k0 = 0
        if (VEC) {
#pragma unroll
            for (int i = 0; i < 2; i++) {
                int idx = tid + i * 256;
                int r = idx >> 2, c4 = idx & 3;
                int gm = m0 + r;
                ra[i] = (gm < M) ? *(const float4*)&A[(size_t)gm * K + c4 * 4]
                                 : make_float4(0.f, 0.f, 0.f, 0.f);
            }
        } else {
#pragma unroll
            for (int i = 0; i < 8; i++) {
                int idx = tid + i * 256;
                int r = idx >> 4, c = idx & 15;
                int gm = m0 + r;
                a_s[i] = (gm < M && c < K) ? A[(size_t)gm * K + c] : 0.f;
            }
        }
        {
            int r = tid >> 4, c4 = tid & 15;
            rb = (r < K) ? *(const float4*)&B[(size_t)r * N + n0 + c4 * 4]
                         : make_float4(0.f, 0.f, 0.f, 0.f);
        }

        for (int k0 = 0; k0 < K; k0 += 16) {
            // commit staged regs to smem
            if (VEC) {
#pragma unroll
                for (int i = 0; i < 2; i++) {
                    int idx = tid + i * 256;
                    int r = idx >> 2, c4 = idx & 3;
                    As[c4 * 4 + 0][r] = ra[i].x;
                    As[c4 * 4 + 1][r] = ra[i].y;
                    As[c4 * 4 + 2][r] = ra[i].z;
                    As[c4 * 4 + 3][r] = ra[i].w;
                }
            } else {
#pragma unroll
                for (int i = 0; i < 8; i++) {
                    int idx = tid + i * 256;
                    int r = idx >> 4, c = idx & 15;
                    As[c][r] = a_s[i];
                }
            }
            {
                int r = tid >> 4, c4 = tid & 15;
                *(float4*)&Bs[r][c4 * 4] = rb;
            }
            __syncthreads();

            int nk = k0 + 16;
            if (nk < K) {
                if (VEC) {
#pragma unroll
                    for (int i = 0; i < 2; i++) {
                        int idx = tid + i * 256;
                        int r = idx >> 2, c4 = idx & 3;
                        int gm = m0 + r;
                        ra[i] = (gm < M) ? *(const float4*)&A[(size_t)gm * K + nk + c4 * 4]
                                         : make_float4(0.f, 0.f, 0.f, 0.f);
                    }
                } else {
#pragma unroll
                    for (int i = 0; i < 8; i++) {
                        int idx = tid + i * 256;
                        int r = idx >> 4, c = idx & 15;
                        int gm = m0 + r;
                        a_s[i] = (gm < M && nk + c < K) ? A[(size_t)gm * K + nk + c] : 0.f;
                    }
                }
                {
                    int r = tid >> 4, c4 = tid & 15;
                    rb = (nk + r < K) ? *(const float4*)&B[(size_t)(nk + r) * N + n0 + c4 * 4]
                                      : make_float4(0.f, 0.f, 0.f, 0.f);
                }
            }

#pragma unroll
            for (int k = 0; k < 16; k++) {
                float4 a0 = *(const float4*)&As[k][ty * 8];
                float4 a1 = *(const float4*)&As[k][ty * 8 + 4];
                float4 b4 = *(const float4*)&Bs[k][tx * 4];
                float aa[8] = {a0.x, a0.y, a0.z, a0.w, a1.x, a1.y, a1.z, a1.w};
                float bb[4] = {b4.x, b4.y, b4.z, b4.w};
#pragma unroll
                for (int i = 0; i < 8; i++)
#pragma unroll
                    for (int j = 0; j < 4; j++)
                        acc[i][j] = fmaf(aa[i], bb[j], acc[i][j]);
            }
            __syncthreads();
        }
    }

    float4 bv = make_float4(0.f, 0.f, 0.f, 0.f);
    if (bias) bv = *(const float4*)&bias[n0 + tx * 4];
#pragma unroll
    for (int i = 0; i < 8; i++) {
        int gm = m0 + ty * 8 + i;
        if (gm >= M) continue;
        float4 o;
        o.x = acc[i][0] + bv.x;
        o.y = acc[i][1] + bv.y;
        o.z = acc[i][2] + bv.z;
        o.w = acc[i][3] + bv.w;
        if (relu) {
            o.x = fmaxf(o.x, 0.f); o.y = fmaxf(o.y, 0.f);
            o.z = fmaxf(o.z, 0.f); o.w = fmaxf(o.w, 0.f);
        }
        *(float4*)&C[(size_t)gm * N + n0 + tx * 4] = o;
    }
}

// ------------- fold attention vectors into K-side: v[k,h] = sum_d W[k, h*64+d]*a[h,d] -------------
__global__ void attnvec_kernel(const float* __restrict__ W, const float* __restrict__ al,
                               const float* __restrict__ ar,
                               float* __restrict__ alv, float* __restrict__ arv)
{
    int idx = blockIdx.x * 256 + threadIdx.x;      // 2048 total
    if (idx >= 2048) return;
    int type = idx >> 10;
    int rem = idx & 1023;
    int r = rem >> 8;
    int k = (rem >> 2) & 63;
    int h = rem & 3;
    const float* av = type ? ar : al;
    float s = 0.f;
#pragma unroll 16
    for (int d = 0; d < 64; d++)
        s += W[(size_t)r * 16384 + (size_t)k * 256 + h * 64 + d] * av[r * 256 + h * 64 + d];
    (type ? arv : alv)[r * 256 + k * 4 + h] = s;
}

// ------------- el/er projection for all 4 relations x {el,er}: out[i,4] = X[i,0:64] @ V[64,4] ----
__global__ void vecproj_all_kernel(const float* __restrict__ Xt, const float* __restrict__ Xw,
                                   const float* __restrict__ alv, const float* __restrict__ arv,
                                   float* __restrict__ el, float* __restrict__ er,
                                   int NT, int NW)
{
    int z = blockIdx.y;          // 0..7
    int r = z >> 1, type = z & 1;   // type 0: el (src side), 1: er (dst side)
    const float* X; int n;
    if (type == 0) { X = (r & 1) ? Xt : Xw; n = (r & 1) ? NT : NW; }
    else           { X = (r & 1) ? Xw : Xt; n = (r & 1) ? NW : NT; }
    const float* V = (type ? arv : alv) + r * 256;
    float* out = (type ? er : el) + (size_t)r * MAXN * 4;

    __shared__ float sv[256];
    if (threadIdx.x < 256) sv[threadIdx.x] = V[threadIdx.x];
    __syncthreads();
    int i = blockIdx.x * blockDim.x + threadIdx.x;
    if (i >= n) return;
    const float* x = X + (size_t)i * 64;
    float a0 = 0, a1 = 0, a2 = 0, a3 = 0;
#pragma unroll 16
    for (int k = 0; k < 64; k++) {
        float xv = __ldg(&x[k]);
        a0 += xv * sv[k * 4 + 0];
        a1 += xv * sv[k * 4 + 1];
        a2 += xv * sv[k * 4 + 2];
        a3 += xv * sv[k * 4 + 3];
    }
    *(float4*)(out + (size_t)i * 4) = make_float4(a0, a1, a2, a3);
}

// ---------------- CSR build ----------------
__global__ void hist_kernel(const int* __restrict__ edges, int* __restrict__ cnt, int E, int n)
{
    for (int idx = blockIdx.x * blockDim.x + threadIdx.x; idx < 4 * E; idx += gridDim.x * blockDim.x) {
        int r = idx / E, i = idx - r * E;
        int dst = edges[(size_t)(2 * r + 1) * E + i];
        atomicAdd(&cnt[r * n + dst], 1);
    }
}

__global__ void scan_kernel(const int* __restrict__ cnt, int* __restrict__ rp, int n)
{
    int r = blockIdx.x;
    int t = threadIdx.x;                      // 1024 threads
    int C = (n + 1023) / 1024;
    __shared__ int sums[1024];
    int base = t * C;
    int loc = 0;
    for (int i = 0; i < C; i++) {
        int idx = base + i;
        if (idx < n) loc += cnt[r * n + idx];
    }
    sums[t] = loc;
    __syncthreads();
    for (int off = 1; off < 1024; off <<= 1) {
        int v = (t >= off) ? sums[t - off] : 0;
        __syncthreads();
        sums[t] += v;
        __syncthreads();
    }
    int run = (t == 0) ? 0 : sums[t - 1];
    for (int i = 0; i < C; i++) {
        int idx = base + i;
        if (idx < n) {
            rp[(size_t)r * (n + 1) + idx] = run;
            run += cnt[r * n + idx];
        }
    }
    if (t == 1023) rp[(size_t)r * (n + 1) + n] = sums[1023];
}

__global__ void scatter_kernel(const int* __restrict__ edges, int* __restrict__ cnt,
                               const int* __restrict__ rp, int* __restrict__ col, int E, int n)
{
    for (int idx = blockIdx.x * blockDim.x + threadIdx.x; idx < 4 * E; idx += gridDim.x * blockDim.x) {
        int r = idx / E, i = idx - r * E;
        int src = edges[(size_t)(2 * r) * E + i];
        int dst = edges[(size_t)(2 * r + 1) * E + i];
        int pos = rp[(size_t)r * (n + 1) + dst] + atomicAdd(&cnt[r * n + dst], 1);
        col[(size_t)r * E + pos] = src;
    }
}

// ---------------- GAT aggregation: warp per dst, both node types, two relations fused ----------
__device__ __forceinline__ float lrelu(float x) { return x > 0.f ? x : 0.2f * x; }

__global__ void gat_agg_kernel(float* __restrict__ Ot, float* __restrict__ Ow,
                               const float* __restrict__ hs,
                               const float* __restrict__ el, const float* __restrict__ er,
                               const int* __restrict__ rp, const int* __restrict__ col,
                               const float* __restrict__ gb, int NT, int NW, int E)
{
    const size_t HOF = (size_t)MAXN * 256;
    const size_t EO4 = (size_t)MAXN * 4;
    int yt = blockIdx.y;                 // 0 = tx dst (rel 0,2), 1 = w dst (rel 1,3)
    int n = yt ? NW : NT;
    float* out = yt ? Ow : Ot;
    int ra = yt, rb = yt + 2;

    int w = (blockIdx.x * blockDim.x + threadIdx.x) >> 5;
    int lane = threadIdx.x & 31;
    if (w >= n) return;

    float4 acc0 = make_float4(0.f, 0.f, 0.f, 0.f);
    float4 acc1 = make_float4(0.f, 0.f, 0.f, 0.f);

#pragma unroll
    for (int q = 0; q < 2; q++) {
        int rel = q ? rb : ra;
        const float* H   = hs + (size_t)rel * HOF;
        const float* elr = el + (size_t)rel * EO4;
        const float* err = er + (size_t)rel * EO4;
        const int* rpr   = rp + (size_t)rel * (MAXN + 1);
        const int* colr  = col + (size_t)rel * E;

        int s0 = rpr[w], s1 = rpr[w + 1];
        if (s1 <= s0) continue;

        float4 e4 = *(const float4*)(err + (size_t)w * 4);
        float er0 = e4.x, er1 = e4.y, er2 = e4.z, er3 = e4.w;

        // pass 1: per-head max
        float m0 = -1e30f, m1 = -1e30f, m2 = -1e30f, m3 = -1e30f;
        for (int e = s0 + lane; e < s1; e += 32) {
            int s = colr[e];
            float4 l4 = *(const float4*)(elr + (size_t)s * 4);
            m0 = fmaxf(m0, lrelu(l4.x + er0));
            m1 = fmaxf(m1, lrelu(l4.y + er1));
            m2 = fmaxf(m2, lrelu(l4.z + er2));
            m3 = fmaxf(m3, lrelu(l4.w + er3));
        }
#pragma unroll
        for (int o = 16; o; o >>= 1) {
            m0 = fmaxf(m0, __shfl_xor_sync(0xffffffffu, m0, o));
            m1 = fmaxf(m1, __shfl_xor_sync(0xffffffffu, m1, o));
            m2 = fmaxf(m2, __shfl_xor_sync(0xffffffffu, m2, o));
            m3 = fmaxf(m3, __shfl_xor_sync(0xffffffffu, m3, o));
        }
        // pass 2: per-head sum of exp
        float z0 = 0, z1 = 0, z2 = 0, z3 = 0;
        for (int e = s0 + lane; e < s1; e += 32) {
            int s = colr[e];
            float4 l4 = *(const float4*)(elr + (size_t)s * 4);
            z0 += __expf(lrelu(l4.x + er0) - m0);
            z1 += __expf(lrelu(l4.y + er1) - m1);
            z2 += __expf(lrelu(l4.z + er2) - m2);
            z3 += __expf(lrelu(l4.w + er3) - m3);
        }
#pragma unroll
        for (int o = 16; o; o >>= 1) {
            z0 += __shfl_xor_sync(0xffffffffu, z0, o);
            z1 += __shfl_xor_sync(0xffffffffu, z1, o);
            z2 += __shfl_xor_sync(0xffffffffu, z2, o);
            z3 += __shfl_xor_sync(0xffffffffu, z3, o);
        }
        float i0 = 1.f / z0, i1 = 1.f / z1, i2 = 1.f / z2, i3 = 1.f / z3;

        // pass 3: weighted accumulate. lane owns float4 channels [lane*4, lane*4+4) and +128.
        for (int e = s0; e < s1; e++) {
            int s = colr[e];
            float4 l4 = *(const float4*)(elr + (size_t)s * 4);
            float a0 = __expf(lrelu(l4.x + er0) - m0) * i0;
            float a1 = __expf(lrelu(l4.y + er1) - m1) * i1;
            float a2 = __expf(lrelu(l4.z + er2) - m2) * i2;
            float a3 = __expf(lrelu(l4.w + er3) - m3) * i3;
            float wA = (lane < 16) ? a0 : a1;   // head of channels lane*4..+3
            float wB = (lane < 16) ? a2 : a3;   // head of channels 128+lane*4..+3
            const float4* hp = (const float4*)(H + (size_t)s * 256);
            float4 h0 = hp[lane];
            float4 h1 = hp[lane + 32];
            acc0.x = fmaf(wA, h0.x, acc0.x); acc0.y = fmaf(wA, h0.y, acc0.y);
            acc0.z = fmaf(wA, h0.z, acc0.z); acc0.w = fmaf(wA, h0.w, acc0.w);
            acc1.x = fmaf(wB, h1.x, acc1.x); acc1.y = fmaf(wB, h1.y, acc1.y);
            acc1.z = fmaf(wB, h1.z, acc1.z); acc1.w = fmaf(wB, h1.w, acc1.w);
        }
    }

    const float4* ba4 = (const float4*)(gb + (size_t)ra * 256);
    const float4* bb4 = (const float4*)(gb + (size_t)rb * 256);
    float4* op = (float4*)(out + (size_t)w * 256);
    {
        float4 x = ba4[lane], y = bb4[lane];
        float4 o;
        o.x = fmaxf(0.f, 0.5f * acc0.x + 0.5f * (x.x + y.x));
        o.y = fmaxf(0.f, 0.5f * acc0.y + 0.5f * (x.y + y.y));
        o.z = fmaxf(0.f, 0.5f * acc0.z + 0.5f * (x.z + y.z));
        o.w = fmaxf(0.f, 0.5f * acc0.w + 0.5f * (x.w + y.w));
        op[lane] = o;
    }
    {
        float4 x = ba4[lane + 32], y = bb4[lane + 32];
        float4 o;
        o.x = fmaxf(0.f, 0.5f * acc1.x + 0.5f * (x.x + y.x));
        o.y = fmaxf(0.f, 0.5f * acc1.y + 0.5f * (x.y + y.y));
        o.z = fmaxf(0.f, 0.5f * acc1.z + 0.5f * (x.z + y.z));
        o.w = fmaxf(0.f, 0.5f * acc1.w + 0.5f * (x.w + y.w));
        op[lane + 32] = o;
    }
}

// ---------------- SAGE mean aggregation for all 4 relations, warp per dst ----------------
__global__ void sage_mean_all_kernel(float* __restrict__ hs,
                                     const float* __restrict__ Xt, const float* __restrict__ Xw,
                                     const int* __restrict__ rp, const int* __restrict__ col,
                                     int NT, int NW, int E)
{
    const size_t HOF = (size_t)MAXN * 256;
    int r = blockIdx.y;                      // relation
    const float* X = (r & 1) ? Xt : Xw;      // src type: odd relations have tx src
    int n = (r & 1) ? NW : NT;
    float* out = hs + (size_t)r * HOF;
    const int* rpr = rp + (size_t)r * (MAXN + 1);
    const int* colr = col + (size_t)r * E;

    int w = (blockIdx.x * blockDim.x + threadIdx.x) >> 5;
    int lane = threadIdx.x & 31;
    if (w >= n) return;
    int s0 = rpr[w], s1 = rpr[w + 1];
    float4 a0 = make_float4(0.f, 0.f, 0.f, 0.f);
    float4 a1 = make_float4(0.f, 0.f, 0.f, 0.f);
    for (int e = s0; e < s1; e++) {
        int s = colr[e];
        const float4* xp = (const float4*)(X + (size_t)s * 256);
        float4 h0 = xp[lane], h1 = xp[lane + 32];
        a0.x += h0.x; a0.y += h0.y; a0.z += h0.z; a0.w += h0.w;
        a1.x += h1.x; a1.y += h1.y; a1.z += h1.z; a1.w += h1.w;
    }
    float inv = 1.f / fmaxf((float)(s1 - s0), 1.f);
    float4* op = (float4*)(out + (size_t)w * 256);
    op[lane]      = make_float4(a0.x * inv, a0.y * inv, a0.z * inv, a0.w * inv);
    op[lane + 32] = make_float4(a1.x * inv, a1.y * inv, a1.z * inv, a1.w * inv);
}

// ---------------- weight pre-add for fused SAGE1 ----------------
__global__ void wsum_kernel(const float* __restrict__ Ws, const float* __restrict__ b,
                            float* __restrict__ wsum, float* __restrict__ bsum)
{
    int i = blockIdx.x * 256 + threadIdx.x;
    if (i < 16384) wsum[i] = Ws[i] + Ws[2 * 16384 + i];                 // rel 0 + 2
    else if (i < 32768) { int j = i - 16384; wsum[i] = Ws[16384 + j] + Ws[3 * 16384 + j]; }
    if (i < 64) bsum[i] = b[i] + b[2 * 64 + i];
    else if (i < 128) { int j = i - 64; bsum[i] = b[64 + j] + b[3 * 64 + j]; }
}

// ---------------- final SAGE (output dim 2), warp per row ----------------
__global__ void sage2_kernel(float* __restrict__ out, const float* __restrict__ Xd,
                             const float* __restrict__ hA, const float* __restrict__ hB,
                             const float* __restrict__ WsA, const float* __restrict__ WsB,
                             const float* __restrict__ WnA, const float* __restrict__ WnB,
                             const float* __restrict__ bA, const float* __restrict__ bB, int n)
{
    __shared__ float sw[3][512];
    for (int i = threadIdx.x; i < 512; i += blockDim.x) {
        sw[0][i] = WsA[i] + WsB[i];
        sw[1][i] = WnA[i];
        sw[2][i] = WnB[i];
    }
    __syncthreads();
    int w = (blockIdx.x * blockDim.x + threadIdx.x) >> 5;
    int lane = threadIdx.x & 31;
    if (w >= n) return;
    float a0 = 0, a1 = 0;
    for (int k = lane; k < 256; k += 32) {
        float x = Xd[(size_t)w * 256 + k];
        a0 += x * sw[0][2 * k];     a1 += x * sw[0][2 * k + 1];
        float u = hA[(size_t)w * 256 + k];
        a0 += u * sw[1][2 * k];     a1 += u * sw[1][2 * k + 1];
        float v = hB[(size_t)w * 256 + k];
        a0 += v * sw[2][2 * k];     a1 += v * sw[2][2 * k + 1];
    }
#pragma unroll
    for (int o = 16; o; o >>= 1) {
        a0 += __shfl_xor_sync(0xffffffffu, a0, o);
        a1 += __shfl_xor_sync(0xffffffffu, a1, o);
    }
    if (lane == 0) {
        out[(size_t)w * 2 + 0] = a0 + bA[0] + bB[0];
        out[(size_t)w * 2 + 1] = a1 + bA[1] + bB[1];
    }
}

// ---------------- host helpers ----------------
static void gemm1(const float* A, const float* B, float* C, const float* bias,
                  int M, int N, int K, int relu)
{
    GSeg s{A, B};
    dim3 g((N + 63) / 64, (M + 127) / 128);
    if ((K & 15) == 0)
        gemm_tile_kernel<true><<<g, 256>>>(s, s, s, 1, C, bias, M, N, K, relu);
    else
        gemm_tile_kernel<false><<<g, 256>>>(s, s, s, 1, C, bias, M, N, K, relu);
}

static void gemm3(const float* A0, const float* B0, const float* A1, const float* B1,
                  const float* A2, const float* B2, float* C, const float* bias,
                  int M, int N, int K, int relu)
{
    GSeg s0{A0, B0}, s1{A1, B1}, s2{A2, B2};
    dim3 g((N + 63) / 64, (M + 127) / 128);
    gemm_tile_kernel<true><<<g, 256>>>(s0, s1, s2, 3, C, bias, M, N, K, relu);
}

static void gat_layer(const float* gW, const float* gal, const float* gar, const float* gb,
                      const float* Xt, const float* Xw, float* Ot, float* Ow,
                      float* hs, float* el, float* er, float* alv, float* arv,
                      const int* rp, const int* col, int NT, int NW, int E)
{
    const size_t HOF = (size_t)MAXN * 256;
    attnvec_kernel<<<8, 256>>>(gW, gal, gar, alv, arv);
    for (int r = 0; r < 4; r++) {
        const float* Xs = (r & 1) ? Xt : Xw;
        int Ns = (r & 1) ? NT : NW;
        gemm1(Xs, gW + (size_t)r * 64 * 256, hs + (size_t)r * HOF, nullptr, Ns, 256, 64, 0);
    }
    int nmax = NT > NW ? NT : NW;
    dim3 gv((nmax + 255) / 256, 8);
    vecproj_all_kernel<<<gv, 256>>>(Xt, Xw, alv, arv, el, er, NT, NW);
    dim3 ga((nmax + 7) / 8, 2);
    gat_agg_kernel<<<ga, 256>>>(Ot, Ow, hs, el, er, rp, col, gb, NT, NW, E);
}

extern "C" void kernel_launch(void* const* d_in, const int* in_sizes, int n_in,
                              void* d_out, int out_size)
{
    const float* tx_feat  = (const float*)d_in[0];
    const float* w_feat   = (const float*)d_in[1];
    const int*   edges    = (const int*)d_in[2];
    const float* tx_W     = (const float*)d_in[3];
    const float* tx_b     = (const float*)d_in[4];
    const float* w_W      = (const float*)d_in[5];
    const float* w_b      = (const float*)d_in[6];
    const float* gat1_W   = (const float*)d_in[7];
    const float* gat1_al  = (const float*)d_in[8];
    const float* gat1_ar  = (const float*)d_in[9];
    const float* gat1_b   = (const float*)d_in[10];
    const float* sage1_Ws = (const float*)d_in[11];
    const float* sage1_Wn = (const float*)d_in[12];
    const float* sage1_b  = (const float*)d_in[13];
    const float* gat2_W   = (const float*)d_in[14];
    const float* gat2_al  = (const float*)d_in[15];
    const float* gat2_ar  = (const float*)d_in[16];
    const float* gat2_b   = (const float*)d_in[17];
    const float* sage2_Ws = (const float*)d_in[18];
    const float* sage2_Wn = (const float*)d_in[19];
    const float* sage2_b  = (const float*)d_in[20];

    int NT = in_sizes[0] / 166;
    int NW = in_sizes[1] / 56;
    int E  = in_sizes[2] / 8;
    if (NT > MAXN) NT = MAXN;
    if (NW > MAXN) NW = MAXN;
    if (E > MAXE) E = MAXE;

    float *t0, *w0, *t1, *w1, *hs, *el, *er, *alv, *arv, *wsum, *bsum;
    int *cnt, *rp, *col;
    cudaGetSymbolAddress((void**)&t0, d_t0);
    cudaGetSymbolAddress((void**)&w0, d_w0);
    cudaGetSymbolAddress((void**)&t1, d_t1);
    cudaGetSymbolAddress((void**)&w1, d_w1);
    cudaGetSymbolAddress((void**)&hs, d_hs);
    cudaGetSymbolAddress((void**)&el, d_el);
    cudaGetSymbolAddress((void**)&er, d_er);
    cudaGetSymbolAddress((void**)&alv, d_alv);
    cudaGetSymbolAddress((void**)&arv, d_arv);
    cudaGetSymbolAddress((void**)&wsum, d_wsum);
    cudaGetSymbolAddress((void**)&bsum, d_bsum);
    cudaGetSymbolAddress((void**)&cnt, d_cnt);
    cudaGetSymbolAddress((void**)&rp, d_rpv);
    cudaGetSymbolAddress((void**)&col, d_colv);

    const size_t HOF = (size_t)MAXN * 256;
    float* fout = (float*)d_out;
    int nmax = NT > NW ? NT : NW;

    // ---- CSR build (per relation, dst-sorted) ----
    cudaMemsetAsync(cnt, 0, 4 * (size_t)MAXN * sizeof(int));
    hist_kernel<<<(4 * E + 255) / 256, 256>>>(edges, cnt, E, NT);
    scan_kernel<<<4, 1024>>>(cnt, rp, NT);
    cudaMemsetAsync(cnt, 0, 4 * (size_t)MAXN * sizeof(int));
    scatter_kernel<<<(4 * E + 255) / 256, 256>>>(edges, cnt, rp, col, E, NT);

    // ---- S0: input projections (relu) -> width 64 ----
    gemm1(tx_feat, tx_W, t0, tx_b, NT, 64, 166, 1);
    gemm1(w_feat,  w_W,  w0, w_b,  NW, 64, 56,  1);

    // ---- S1: hetero GAT1 (64 -> 256, relu fused) ----
    gat_layer(gat1_W, gat1_al, gat1_ar, gat1_b, t0, w0, t1, w1,
              hs, el, er, alv, arv, rp, col, NT, NW, E);

    // ---- S2: hetero SAGE1 (256 -> 64, fully fused 3-segment GEMM, relu) ----
    {
        dim3 gm4((nmax + 7) / 8, 4);
        sage_mean_all_kernel<<<gm4, 256>>>(hs, t1, w1, rp, col, NT, NW, E);
        wsum_kernel<<<128, 256>>>(sage1_Ws, sage1_b, wsum, bsum);
        gemm3(t1, wsum,          hs + 0 * HOF, sage1_Wn + 0 * 16384,
              hs + 2 * HOF, sage1_Wn + 2 * 16384, t0, bsum,      NT, 64, 256, 1);
        gemm3(w1, wsum + 16384,  hs + 1 * HOF, sage1_Wn + 1 * 16384,
              hs + 3 * HOF, sage1_Wn + 3 * 16384, w0, bsum + 64, NW, 64, 256, 1);
    }

    // ---- S3: hetero GAT2 (64 -> 256, relu fused) ----
    gat_layer(gat2_W, gat2_al, gat2_ar, gat2_b, t0, w0, t1, w1,
              hs, el, er, alv, arv, rp, col, NT, NW, E);

    // ---- S4: hetero SAGE2 (256 -> 2), no relu ----
    {
        dim3 gm4((nmax + 7) / 8, 4);
        sage_mean_all_kernel<<<gm4, 256>>>(hs, t1, w1, rp, col, NT, NW, E);
        sage2_kernel<<<(NT + 7) / 8, 256>>>(fout, t1, hs + 0 * HOF, hs + 2 * HOF,
            sage2_Ws + 0 * 512, sage2_Ws + 2 * 512, sage2_Wn + 0 * 512, sage2_Wn + 2 * 512,
            sage2_b + 0, sage2_b + 4, NT);
        sage2_kernel<<<(NW + 7) / 8, 256>>>(fout + (size_t)NT * 2, w1, hs + 1 * HOF, hs + 3 * HOF,
            sage2_Ws + 1 * 512, sage2_Ws + 3 * 512, sage2_Wn + 1 * 512, sage2_Wn + 3 * 512,
            sage2_b + 2, sage2_b + 6, NW);
    }
}

// round 4
// speedup vs baseline: 1.5305x; 1.1375x over previous
#include <cuda_runtime.h>
#include <cstdint>
#include <cstddef>

#define MAXN 50000
#define MAXE 400000

// ---------------- persistent device scratch ----------------
__device__ float d_t0[(size_t)MAXN * 256];
__device__ float d_w0[(size_t)MAXN * 256];
__device__ float d_t1[(size_t)MAXN * 256];
__device__ float d_w1[(size_t)MAXN * 256];
__device__ float d_hs[4 * (size_t)MAXN * 256];   // GAT H buffers / SAGE1 y buffers
__device__ float d_el[4 * (size_t)MAXN * 4];
__device__ float d_er[4 * (size_t)MAXN * 4];
__device__ float d_alv[4 * 64 * 4];
__device__ float d_arv[4 * 64 * 4];
__device__ float d_wsum[2 * 256 * 64];
__device__ float d_bsum[128];
__device__ int   d_cnt[4 * MAXN];
__device__ int   d_rpv[4 * (MAXN + 1)];
__device__ int   d_colv[4 * MAXE];

// ---------------- GEMM: C[M,N] = sum_s A_s[M,K] @ B_s[K,N] (+bias)(relu) --------------
// 8x8 micro-tile, BK=16, register-staged prefetch. BM*BN/64 == 256 threads.
struct GSeg { const float* A; const float* B; };

template<int BM, int BN, bool VEC>
__launch_bounds__(256, 2)
__global__ void gemmT_kernel(GSeg s0, GSeg s1, GSeg s2, int nseg,
                             float* __restrict__ C, const float* __restrict__ bias,
                             int M, int N, int K, int relu)
{
    constexpr int TX  = BN / 8;
    constexpr int AF4 = BM / 64;     // float4 per thread for A (VEC path)
    constexpr int BF4 = BN / 64;     // float4 per thread for B (VEC path)
    constexpr int ASC = BM / 16;     // scalars per thread for A (scalar path)
    constexpr int BSC = BN / 16;     // scalars per thread for B

    __shared__ float As[16][BM];
    __shared__ float Bs[16][BN];

    const int tid = threadIdx.x;
    const int tx = tid % TX, ty = tid / TX;
    const int m0 = blockIdx.y * BM, n0 = blockIdx.x * BN;

    float acc[8][8];
#pragma unroll
    for (int i = 0; i < 8; i++)
#pragma unroll
        for (int j = 0; j < 8; j++) acc[i][j] = 0.f;

    for (int seg = 0; seg < nseg; seg++) {
        const float* __restrict__ A = (seg == 0) ? s0.A : (seg == 1) ? s1.A : s2.A;
        const float* __restrict__ B = (seg == 0) ? s0.B : (seg == 1) ? s1.B : s2.B;

        float4 ra[AF4 > 0 ? AF4 : 1];
        float4 rb[BF4 > 0 ? BF4 : 1];
        float  as_[ASC];
        float  bs_[BSC];

        // ---- prologue: stage k0 = 0 ----
        if (VEC) {
#pragma unroll
            for (int i = 0; i < AF4; i++) {
                int idx = tid + i * 256;
                int r = idx >> 2, c4 = idx & 3;
                int gm = m0 + r;
                ra[i] = (gm < M) ? *(const float4*)&A[(size_t)gm * K + c4 * 4]
                                 : make_float4(0.f, 0.f, 0.f, 0.f);
            }
#pragma unroll
            for (int i = 0; i < BF4; i++) {
                int idx = tid + i * 256;
                int r = idx / (BN / 4), c4 = idx % (BN / 4);
                rb[i] = *(const float4*)&B[(size_t)r * N + n0 + c4 * 4];
            }
        } else {
#pragma unroll
            for (int i = 0; i < ASC; i++) {
                int idx = tid + i * 256;
                int r = idx >> 4, c = idx & 15;
                int gm = m0 + r;
                as_[i] = (gm < M && c < K) ? A[(size_t)gm * K + c] : 0.f;
            }
#pragma unroll
            for (int i = 0; i < BSC; i++) {
                int idx = tid + i * 256;
                int r = idx / BN, c = idx % BN;
                bs_[i] = (r < K) ? B[(size_t)r * N + n0 + c] : 0.f;
            }
        }

        for (int k0 = 0; k0 < K; k0 += 16) {
            // ---- commit staged regs to smem ----
            if (VEC) {
#pragma unroll
                for (int i = 0; i < AF4; i++) {
                    int idx = tid + i * 256;
                    int r = idx >> 2, c4 = idx & 3;
                    As[c4 * 4 + 0][r] = ra[i].x;
                    As[c4 * 4 + 1][r] = ra[i].y;
                    As[c4 * 4 + 2][r] = ra[i].z;
                    As[c4 * 4 + 3][r] = ra[i].w;
                }
#pragma unroll
                for (int i = 0; i < BF4; i++) {
                    int idx = tid + i * 256;
                    int r = idx / (BN / 4), c4 = idx % (BN / 4);
                    *(float4*)&Bs[r][c4 * 4] = rb[i];
                }
            } else {
#pragma unroll
                for (int i = 0; i < ASC; i++) {
                    int idx = tid + i * 256;
                    int r = idx >> 4, c = idx & 15;
                    As[c][r] = as_[i];
                }
#pragma unroll
                for (int i = 0; i < BSC; i++) {
                    int idx = tid + i * 256;
                    int r = idx / BN, c = idx % BN;
                    Bs[r][c] = bs_[i];
                }
            }
            __syncthreads();

            // ---- stage next k-tile ----
            int nk = k0 + 16;
            if (nk < K) {
                if (VEC) {
#pragma unroll
                    for (int i = 0; i < AF4; i++) {
                        int idx = tid + i * 256;
                        int r = idx >> 2, c4 = idx & 3;
                        int gm = m0 + r;
                        ra[i] = (gm < M) ? *(const float4*)&A[(size_t)gm * K + nk + c4 * 4]
                                         : make_float4(0.f, 0.f, 0.f, 0.f);
                    }
#pragma unroll
                    for (int i = 0; i < BF4; i++) {
                        int idx = tid + i * 256;
                        int r = idx / (BN / 4), c4 = idx % (BN / 4);
                        rb[i] = *(const float4*)&B[(size_t)(nk + r) * N + n0 + c4 * 4];
                    }
                } else {
#pragma unroll
                    for (int i = 0; i < ASC; i++) {
                        int idx = tid + i * 256;
                        int r = idx >> 4, c = idx & 15;
                        int gm = m0 + r;
                        as_[i] = (gm < M && nk + c < K) ? A[(size_t)gm * K + nk + c] : 0.f;
                    }
#pragma unroll
                    for (int i = 0; i < BSC; i++) {
                        int idx = tid + i * 256;
                        int r = idx / BN, c = idx % BN;
                        bs_[i] = (nk + r < K) ? B[(size_t)(nk + r) * N + n0 + c] : 0.f;
                    }
                }
            }

            // ---- compute 16 k-iters ----
#pragma unroll
            for (int k = 0; k < 16; k++) {
                float4 a0 = *(const float4*)&As[k][ty * 4];
                float4 a1 = *(const float4*)&As[k][ty * 4 + BM / 2];
                float4 b0 = *(const float4*)&Bs[k][tx * 4];
                float4 b1 = *(const float4*)&Bs[k][tx * 4 + BN / 2];
                float aa[8] = {a0.x, a0.y, a0.z, a0.w, a1.x, a1.y, a1.z, a1.w};
                float bb[8] = {b0.x, b0.y, b0.z, b0.w, b1.x, b1.y, b1.z, b1.w};
#pragma unroll
                for (int i = 0; i < 8; i++)
#pragma unroll
                    for (int j = 0; j < 8; j++)
                        acc[i][j] = fmaf(aa[i], bb[j], acc[i][j]);
            }
            __syncthreads();
        }
    }

    // ---- epilogue ----
    float4 bv0 = make_float4(0.f, 0.f, 0.f, 0.f), bv1 = bv0;
    if (bias) {
        bv0 = *(const float4*)&bias[n0 + tx * 4];
        bv1 = *(const float4*)&bias[n0 + tx * 4 + BN / 2];
    }
#pragma unroll
    for (int half = 0; half < 2; half++) {
#pragma unroll
        for (int i = 0; i < 4; i++) {
            int gm = m0 + half * (BM / 2) + ty * 4 + i;
            if (gm >= M) continue;
            int ii = half * 4 + i;
            float4 o0 = make_float4(acc[ii][0] + bv0.x, acc[ii][1] + bv0.y,
                                    acc[ii][2] + bv0.z, acc[ii][3] + bv0.w);
            float4 o1 = make_float4(acc[ii][4] + bv1.x, acc[ii][5] + bv1.y,
                                    acc[ii][6] + bv1.z, acc[ii][7] + bv1.w);
            if (relu) {
                o0.x = fmaxf(o0.x, 0.f); o0.y = fmaxf(o0.y, 0.f);
                o0.z = fmaxf(o0.z, 0.f); o0.w = fmaxf(o0.w, 0.f);
                o1.x = fmaxf(o1.x, 0.f); o1.y = fmaxf(o1.y, 0.f);
                o1.z = fmaxf(o1.z, 0.f); o1.w = fmaxf(o1.w, 0.f);
            }
            *(float4*)&C[(size_t)gm * N + n0 + tx * 4] = o0;
            *(float4*)&C[(size_t)gm * N + n0 + tx * 4 + BN / 2] = o1;
        }
    }
}

// ------------- fold attention vectors into K-side: v[k,h] = sum_d W[k, h*64+d]*a[h,d] --------
__global__ void attnvec_kernel(const float* __restrict__ W, const float* __restrict__ al,
                               const float* __restrict__ ar,
                               float* __restrict__ alv, float* __restrict__ arv)
{
    int idx = blockIdx.x * 256 + threadIdx.x;      // 2048 total
    if (idx >= 2048) return;
    int type = idx >> 10;
    int rem = idx & 1023;
    int r = rem >> 8;
    int k = (rem >> 2) & 63;
    int h = rem & 3;
    const float* av = type ? ar : al;
    float s = 0.f;
#pragma unroll 16
    for (int d = 0; d < 64; d++)
        s += W[(size_t)r * 16384 + (size_t)k * 256 + h * 64 + d] * av[r * 256 + h * 64 + d];
    (type ? arv : alv)[r * 256 + k * 4 + h] = s;
}

// ------------- fused el/er projection: one X read computes 4 vec-projections -------------
__global__ void vecproj_fused_kernel(const float* __restrict__ Xt, const float* __restrict__ Xw,
                                     const float* __restrict__ alv, const float* __restrict__ arv,
                                     float* __restrict__ el, float* __restrict__ er,
                                     int NT, int NW)
{
    int type = blockIdx.y;                 // 0 = tx nodes, 1 = w nodes
    const float* X = type ? Xw : Xt;
    int n = type ? NW : NT;
    int e0 = type ? 0 : 1;                 // el relations {e0, e0+2} (this type is src)
    int r0 = type ? 1 : 0;                 // er relations {r0, r0+2} (this type is dst)

    __shared__ float sv[4][256];
    for (int i = threadIdx.x; i < 1024; i += blockDim.x) {
        int v = i >> 8, c = i & 255;
        const float* src = (v < 2) ? (alv + (e0 + 2 * (v & 1)) * 256)
                                   : (arv + (r0 + 2 * (v & 1)) * 256);
        sv[v][c] = src[c];
    }
    __syncthreads();
    int i = blockIdx.x * blockDim.x + threadIdx.x;
    if (i >= n) return;
    const float* x = X + (size_t)i * 64;
    float a[4][4] = {};
#pragma unroll 8
    for (int k = 0; k < 64; k++) {
        float xv = __ldg(&x[k]);
#pragma unroll
        for (int v = 0; v < 4; v++) {
            float4 s4 = *(const float4*)&sv[v][k * 4];
            a[v][0] += xv * s4.x; a[v][1] += xv * s4.y;
            a[v][2] += xv * s4.z; a[v][3] += xv * s4.w;
        }
    }
    *(float4*)&el[(size_t)(e0)     * MAXN * 4 + (size_t)i * 4] = make_float4(a[0][0], a[0][1], a[0][2], a[0][3]);
    *(float4*)&el[(size_t)(e0 + 2) * MAXN * 4 + (size_t)i * 4] = make_float4(a[1][0], a[1][1], a[1][2], a[1][3]);
    *(float4*)&er[(size_t)(r0)     * MAXN * 4 + (size_t)i * 4] = make_float4(a[2][0], a[2][1], a[2][2], a[2][3]);
    *(float4*)&er[(size_t)(r0 + 2) * MAXN * 4 + (size_t)i * 4] = make_float4(a[3][0], a[3][1], a[3][2], a[3][3]);
}

// ---------------- CSR build ----------------
__global__ void hist_kernel(const int* __restrict__ edges, int* __restrict__ cnt, int E, int n)
{
    for (int idx = blockIdx.x * blockDim.x + threadIdx.x; idx < 4 * E; idx += gridDim.x * blockDim.x) {
        int r = idx / E, i = idx - r * E;
        int dst = edges[(size_t)(2 * r + 1) * E + i];
        atomicAdd(&cnt[r * n + dst], 1);
    }
}

__global__ void scan_kernel(const int* __restrict__ cnt, int* __restrict__ rp, int n)
{
    int r = blockIdx.x;
    int t = threadIdx.x;                      // 1024 threads
    int C = (n + 1023) / 1024;
    __shared__ int sums[1024];
    int base = t * C;
    int loc = 0;
    for (int i = 0; i < C; i++) {
        int idx = base + i;
        if (idx < n) loc += cnt[r * n + idx];
    }
    sums[t] = loc;
    __syncthreads();
    for (int off = 1; off < 1024; off <<= 1) {
        int v = (t >= off) ? sums[t - off] : 0;
        __syncthreads();
        sums[t] += v;
        __syncthreads();
    }
    int run = (t == 0) ? 0 : sums[t - 1];
    for (int i = 0; i < C; i++) {
        int idx = base + i;
        if (idx < n) {
            rp[(size_t)r * (n + 1) + idx] = run;
            run += cnt[r * n + idx];
        }
    }
    if (t == 1023) rp[(size_t)r * (n + 1) + n] = sums[1023];
}

__global__ void scatter_kernel(const int* __restrict__ edges, int* __restrict__ cnt,
                               const int* __restrict__ rp, int* __restrict__ col, int E, int n)
{
    for (int idx = blockIdx.x * blockDim.x + threadIdx.x; idx < 4 * E; idx += gridDim.x * blockDim.x) {
        int r = idx / E, i = idx - r * E;
        int src = edges[(size_t)(2 * r) * E + i];
        int dst = edges[(size_t)(2 * r + 1) * E + i];
        int pos = rp[(size_t)r * (n + 1) + dst] + atomicAdd(&cnt[r * n + dst], 1);
        col[(size_t)r * E + pos] = src;
    }
}

// ---------------- GAT aggregation: warp per dst, both node types, two relations fused --------
__device__ __forceinline__ float lrelu(float x) { return x > 0.f ? x : 0.2f * x; }

__global__ void gat_agg_kernel(float* __restrict__ Ot, float* __restrict__ Ow,
                               const float* __restrict__ hs,
                               const float* __restrict__ el, const float* __restrict__ er,
                               const int* __restrict__ rp, const int* __restrict__ col,
                               const float* __restrict__ gb, int NT, int NW, int E)
{
    const size_t HOF = (size_t)MAXN * 256;
    const size_t EO4 = (size_t)MAXN * 4;
    int yt = blockIdx.y;                 // 0 = tx dst (rel 0,2), 1 = w dst (rel 1,3)
    int n = yt ? NW : NT;
    float* out = yt ? Ow : Ot;
    int ra = yt, rb = yt + 2;

    int w = (blockIdx.x * blockDim.x + threadIdx.x) >> 5;
    int lane = threadIdx.x & 31;
    if (w >= n) return;

    float4 acc0 = make_float4(0.f, 0.f, 0.f, 0.f);
    float4 acc1 = make_float4(0.f, 0.f, 0.f, 0.f);

#pragma unroll
    for (int q = 0; q < 2; q++) {
        int rel = q ? rb : ra;
        const float* H   = hs + (size_t)rel * HOF;
        const float* elr = el + (size_t)rel * EO4;
        const float* err = er + (size_t)rel * EO4;
        const int* rpr   = rp + (size_t)rel * (MAXN + 1);
        const int* colr  = col + (size_t)rel * E;

        int s0 = rpr[w], s1 = rpr[w + 1];
        if (s1 <= s0) continue;

        float4 e4 = *(const float4*)(err + (size_t)w * 4);
        float er0 = e4.x, er1 = e4.y, er2 = e4.z, er3 = e4.w;

        float m0 = -1e30f, m1 = -1e30f, m2 = -1e30f, m3 = -1e30f;
        for (int e = s0 + lane; e < s1; e += 32) {
            int s = colr[e];
            float4 l4 = *(const float4*)(elr + (size_t)s * 4);
            m0 = fmaxf(m0, lrelu(l4.x + er0));
            m1 = fmaxf(m1, lrelu(l4.y + er1));
            m2 = fmaxf(m2, lrelu(l4.z + er2));
            m3 = fmaxf(m3, lrelu(l4.w + er3));
        }
#pragma unroll
        for (int o = 16; o; o >>= 1) {
            m0 = fmaxf(m0, __shfl_xor_sync(0xffffffffu, m0, o));
            m1 = fmaxf(m1, __shfl_xor_sync(0xffffffffu, m1, o));
            m2 = fmaxf(m2, __shfl_xor_sync(0xffffffffu, m2, o));
            m3 = fmaxf(m3, __shfl_xor_sync(0xffffffffu, m3, o));
        }
        float z0 = 0, z1 = 0, z2 = 0, z3 = 0;
        for (int e = s0 + lane; e < s1; e += 32) {
            int s = colr[e];
            float4 l4 = *(const float4*)(elr + (size_t)s * 4);
            z0 += __expf(lrelu(l4.x + er0) - m0);
            z1 += __expf(lrelu(l4.y + er1) - m1);
            z2 += __expf(lrelu(l4.z + er2) - m2);
            z3 += __expf(lrelu(l4.w + er3) - m3);
        }
#pragma unroll
        for (int o = 16; o; o >>= 1) {
            z0 += __shfl_xor_sync(0xffffffffu, z0, o);
            z1 += __shfl_xor_sync(0xffffffffu, z1, o);
            z2 += __shfl_xor_sync(0xffffffffu, z2, o);
            z3 += __shfl_xor_sync(0xffffffffu, z3, o);
        }
        float i0 = 1.f / z0, i1 = 1.f / z1, i2 = 1.f / z2, i3 = 1.f / z3;

        for (int e = s0; e < s1; e++) {
            int s = colr[e];
            float4 l4 = *(const float4*)(elr + (size_t)s * 4);
            float a0 = __expf(lrelu(l4.x + er0) - m0) * i0;
            float a1 = __expf(lrelu(l4.y + er1) - m1) * i1;
            float a2 = __expf(lrelu(l4.z + er2) - m2) * i2;
            float a3 = __expf(lrelu(l4.w + er3) - m3) * i3;
            float wA = (lane < 16) ? a0 : a1;
            float wB = (lane < 16) ? a2 : a3;
            const float4* hp = (const float4*)(H + (size_t)s * 256);
            float4 h0 = hp[lane];
            float4 h1 = hp[lane + 32];
            acc0.x = fmaf(wA, h0.x, acc0.x); acc0.y = fmaf(wA, h0.y, acc0.y);
            acc0.z = fmaf(wA, h0.z, acc0.z); acc0.w = fmaf(wA, h0.w, acc0.w);
            acc1.x = fmaf(wB, h1.x, acc1.x); acc1.y = fmaf(wB, h1.y, acc1.y);
            acc1.z = fmaf(wB, h1.z, acc1.z); acc1.w = fmaf(wB, h1.w, acc1.w);
        }
    }

    const float4* ba4 = (const float4*)(gb + (size_t)ra * 256);
    const float4* bb4 = (const float4*)(gb + (size_t)rb * 256);
    float4* op = (float4*)(out + (size_t)w * 256);
    {
        float4 x = ba4[lane], y = bb4[lane];
        float4 o;
        o.x = fmaxf(0.f, 0.5f * acc0.x + 0.5f * (x.x + y.x));
        o.y = fmaxf(0.f, 0.5f * acc0.y + 0.5f * (x.y + y.y));
        o.z = fmaxf(0.f, 0.5f * acc0.z + 0.5f * (x.z + y.z));
        o.w = fmaxf(0.f, 0.5f * acc0.w + 0.5f * (x.w + y.w));
        op[lane] = o;
    }
    {
        float4 x = ba4[lane + 32], y = bb4[lane + 32];
        float4 o;
        o.x = fmaxf(0.f, 0.5f * acc1.x + 0.5f * (x.x + y.x));
        o.y = fmaxf(0.f, 0.5f * acc1.y + 0.5f * (x.y + y.y));
        o.z = fmaxf(0.f, 0.5f * acc1.z + 0.5f * (x.z + y.z));
        o.w = fmaxf(0.f, 0.5f * acc1.w + 0.5f * (x.w + y.w));
        op[lane + 32] = o;
    }
}

// ---------------- weight pre-add for SAGE1 self branch ----------------
__global__ void wsum_kernel(const float* __restrict__ Ws, const float* __restrict__ b,
                            float* __restrict__ wsum, float* __restrict__ bsum)
{
    int i = blockIdx.x * 256 + threadIdx.x;
    if (i < 16384) wsum[i] = Ws[i] + Ws[2 * 16384 + i];                 // rel 0 + 2
    else if (i < 32768) { int j = i - 16384; wsum[i] = Ws[16384 + j] + Ws[3 * 16384 + j]; }
    if (i < 64) bsum[i] = b[i] + b[2 * 64 + i];
    else if (i < 128) { int j = i - 64; bsum[i] = b[64 + j] + b[3 * 64 + j]; }
}

// ------------- SAGE1 combine: X = relu(X + mean_a(ya) + mean_b(yb)), rows 64-wide ---------
__global__ void sage1_combine_kernel(float* __restrict__ X,
    const float* __restrict__ ya, const float* __restrict__ yb,
    const int* __restrict__ rpa, const int* __restrict__ cola,
    const int* __restrict__ rpb, const int* __restrict__ colb, int n)
{
    int w = (blockIdx.x * blockDim.x + threadIdx.x) >> 5;
    int lane = threadIdx.x & 31;
    if (w >= n) return;
    float mx = 0.f, my = 0.f;
    {
        int s0 = rpa[w], s1 = rpa[w + 1];
        float sx = 0.f, sy = 0.f;
        for (int e = s0; e < s1; e++) {
            int s = cola[e];
            float2 v = *(const float2*)&ya[(size_t)s * 64 + lane * 2];
            sx += v.x; sy += v.y;
        }
        float inv = 1.f / fmaxf((float)(s1 - s0), 1.f);
        mx += sx * inv; my += sy * inv;
    }
    {
        int s0 = rpb[w], s1 = rpb[w + 1];
        float sx = 0.f, sy = 0.f;
        for (int e = s0; e < s1; e++) {
            int s = colb[e];
            float2 v = *(const float2*)&yb[(size_t)s * 64 + lane * 2];
            sx += v.x; sy += v.y;
        }
        float inv = 1.f / fmaxf((float)(s1 - s0), 1.f);
        mx += sx * inv; my += sy * inv;
    }
    float2* xp = (float2*)&X[(size_t)w * 64 + lane * 2];
    float2 xv = *xp;
    xv.x = fmaxf(xv.x + mx, 0.f);
    xv.y = fmaxf(xv.y + my, 0.f);
    *xp = xv;
}

// ------------- SAGE2 projections: self (Ws_a+Ws_b) and two y = X@Wn, all dim 2 -------------
__global__ void proj6_kernel(const float* __restrict__ X,
    const float* __restrict__ WsA, const float* __restrict__ WsB,
    const float* __restrict__ WnA, const float* __restrict__ WnB,
    float* __restrict__ selfO, float* __restrict__ yA, float* __restrict__ yB, int n)
{
    __shared__ float sw[3][512];
    for (int i = threadIdx.x; i < 512; i += blockDim.x) {
        sw[0][i] = WsA[i] + WsB[i];
        sw[1][i] = WnA[i];
        sw[2][i] = WnB[i];
    }
    __syncthreads();
    int w = (blockIdx.x * blockDim.x + threadIdx.x) >> 5;
    int lane = threadIdx.x & 31;
    if (w >= n) return;
    float a[6] = {0.f, 0.f, 0.f, 0.f, 0.f, 0.f};
    for (int k = lane; k < 256; k += 32) {
        float x = X[(size_t)w * 256 + k];
        a[0] += x * sw[0][2 * k]; a[1] += x * sw[0][2 * k + 1];
        a[2] += x * sw[1][2 * k]; a[3] += x * sw[1][2 * k + 1];
        a[4] += x * sw[2][2 * k]; a[5] += x * sw[2][2 * k + 1];
    }
#pragma unroll
    for (int o = 16; o; o >>= 1)
#pragma unroll
        for (int j = 0; j < 6; j++)
            a[j] += __shfl_xor_sync(0xffffffffu, a[j], o);
    if (lane == 0) {
        *(float2*)&selfO[(size_t)w * 2] = make_float2(a[0], a[1]);
        *(float2*)&yA[(size_t)w * 2]    = make_float2(a[2], a[3]);
        *(float2*)&yB[(size_t)w * 2]    = make_float2(a[4], a[5]);
    }
}

// ------------- SAGE2 combine: out = self + bA + bB + mean_a(yA) + mean_b(yB) -------------
__global__ void sage2_combine_kernel(float* __restrict__ out,
    const float* __restrict__ selfO, const float* __restrict__ yA, const float* __restrict__ yB,
    const int* __restrict__ rpa, const int* __restrict__ cola,
    const int* __restrict__ rpb, const int* __restrict__ colb,
    const float* __restrict__ bA, const float* __restrict__ bB, int n)
{
    int w = blockIdx.x * blockDim.x + threadIdx.x;
    if (w >= n) return;
    float2 r = *(const float2*)&selfO[(size_t)w * 2];
    r.x += bA[0] + bB[0];
    r.y += bA[1] + bB[1];
    {
        int s0 = rpa[w], s1 = rpa[w + 1];
        float sx = 0.f, sy = 0.f;
        for (int e = s0; e < s1; e++) {
            float2 v = *(const float2*)&yA[(size_t)cola[e] * 2];
            sx += v.x; sy += v.y;
        }
        float inv = 1.f / fmaxf((float)(s1 - s0), 1.f);
        r.x += sx * inv; r.y += sy * inv;
    }
    {
        int s0 = rpb[w], s1 = rpb[w + 1];
        float sx = 0.f, sy = 0.f;
        for (int e = s0; e < s1; e++) {
            float2 v = *(const float2*)&yB[(size_t)colb[e] * 2];
            sx += v.x; sy += v.y;
        }
        float inv = 1.f / fmaxf((float)(s1 - s0), 1.f);
        r.x += sx * inv; r.y += sy * inv;
    }
    *(float2*)&out[(size_t)w * 2] = r;
}

// ---------------- host helpers ----------------
static void gemm1(const float* A, const float* B, float* C, const float* bias,
                  int M, int N, int K, int relu)
{
    GSeg s{A, B};
    if (N % 128 == 0) {
        dim3 g(N / 128, (M + 127) / 128);
        if (K % 16 == 0) gemmT_kernel<128, 128, true><<<g, 256>>>(s, s, s, 1, C, bias, M, N, K, relu);
        else             gemmT_kernel<128, 128, false><<<g, 256>>>(s, s, s, 1, C, bias, M, N, K, relu);
    } else {
        dim3 g(N / 64, (M + 255) / 256);
        if (K % 16 == 0) gemmT_kernel<256, 64, true><<<g, 256>>>(s, s, s, 1, C, bias, M, N, K, relu);
        else             gemmT_kernel<256, 64, false><<<g, 256>>>(s, s, s, 1, C, bias, M, N, K, relu);
    }
}

static void gat_layer(const float* gW, const float* gal, const float* gar, const float* gb,
                      const float* Xt, const float* Xw, float* Ot, float* Ow,
                      float* hs, float* el, float* er, float* alv, float* arv,
                      const int* rp, const int* col, int NT, int NW, int E)
{
    const size_t HOF = (size_t)MAXN * 256;
    attnvec_kernel<<<8, 256>>>(gW, gal, gar, alv, arv);
    for (int r = 0; r < 4; r++) {
        const float* Xs = (r & 1) ? Xt : Xw;
        int Ns = (r & 1) ? NT : NW;
        gemm1(Xs, gW + (size_t)r * 64 * 256, hs + (size_t)r * HOF, nullptr, Ns, 256, 64, 0);
    }
    int nmax = NT > NW ? NT : NW;
    dim3 gv((nmax + 255) / 256, 2);
    vecproj_fused_kernel<<<gv, 256>>>(Xt, Xw, alv, arv, el, er, NT, NW);
    dim3 ga((nmax + 7) / 8, 2);
    gat_agg_kernel<<<ga, 256>>>(Ot, Ow, hs, el, er, rp, col, gb, NT, NW, E);
}

extern "C" void kernel_launch(void* const* d_in, const int* in_sizes, int n_in,
                              void* d_out, int out_size)
{
    const float* tx_feat  = (const float*)d_in[0];
    const float* w_feat   = (const float*)d_in[1];
    const int*   edges    = (const int*)d_in[2];
    const float* tx_W     = (const float*)d_in[3];
    const float* tx_b     = (const float*)d_in[4];
    const float* w_W      = (const float*)d_in[5];
    const float* w_b      = (const float*)d_in[6];
    const float* gat1_W   = (const float*)d_in[7];
    const float* gat1_al  = (const float*)d_in[8];
    const float* gat1_ar  = (const float*)d_in[9];
    const float* gat1_b   = (const float*)d_in[10];
    const float* sage1_Ws = (const float*)d_in[11];
    const float* sage1_Wn = (const float*)d_in[12];
    const float* sage1_b  = (const float*)d_in[13];
    const float* gat2_W   = (const float*)d_in[14];
    const float* gat2_al  = (const float*)d_in[15];
    const float* gat2_ar  = (const float*)d_in[16];
    const float* gat2_b   = (const float*)d_in[17];
    const float* sage2_Ws = (const float*)d_in[18];
    const float* sage2_Wn = (const float*)d_in[19];
    const float* sage2_b  = (const float*)d_in[20];

    int NT = in_sizes[0] / 166;
    int NW = in_sizes[1] / 56;
    int E  = in_sizes[2] / 8;
    if (NT > MAXN) NT = MAXN;
    if (NW > MAXN) NW = MAXN;
    if (E > MAXE) E = MAXE;

    float *t0, *w0, *t1, *w1, *hs, *el, *er, *alv, *arv, *wsum, *bsum;
    int *cnt, *rp, *col;
    cudaGetSymbolAddress((void**)&t0, d_t0);
    cudaGetSymbolAddress((void**)&w0, d_w0);
    cudaGetSymbolAddress((void**)&t1, d_t1);
    cudaGetSymbolAddress((void**)&w1, d_w1);
    cudaGetSymbolAddress((void**)&hs, d_hs);
    cudaGetSymbolAddress((void**)&el, d_el);
    cudaGetSymbolAddress((void**)&er, d_er);
    cudaGetSymbolAddress((void**)&alv, d_alv);
    cudaGetSymbolAddress((void**)&arv, d_arv);
    cudaGetSymbolAddress((void**)&wsum, d_wsum);
    cudaGetSymbolAddress((void**)&bsum, d_bsum);
    cudaGetSymbolAddress((void**)&cnt, d_cnt);
    cudaGetSymbolAddress((void**)&rp, d_rpv);
    cudaGetSymbolAddress((void**)&col, d_colv);

    float* fout = (float*)d_out;
    const size_t Y64 = (size_t)MAXN * 64;     // SAGE1 y buffer stride inside d_hs
    const int* rp0 = rp;  const int* rp1 = rp + (MAXN + 1);
    const int* rp2 = rp + 2 * (MAXN + 1);  const int* rp3 = rp + 3 * (MAXN + 1);
    const int* col0 = col; const int* col1 = col + (size_t)E;
    const int* col2 = col + 2 * (size_t)E; const int* col3 = col + 3 * (size_t)E;

    // ---- CSR build (per relation, dst-sorted) ----
    cudaMemsetAsync(cnt, 0, 4 * (size_t)MAXN * sizeof(int));
    hist_kernel<<<(4 * E + 255) / 256, 256>>>(edges, cnt, E, NT);
    scan_kernel<<<4, 1024>>>(cnt, rp, NT);
    cudaMemsetAsync(cnt, 0, 4 * (size_t)MAXN * sizeof(int));
    scatter_kernel<<<(4 * E + 255) / 256, 256>>>(edges, cnt, rp, col, E, NT);

    // ---- S0: input projections (relu) -> width 64 ----
    gemm1(tx_feat, tx_W, t0, tx_b, NT, 64, 166, 1);
    gemm1(w_feat,  w_W,  w0, w_b,  NW, 64, 56,  1);

    // ---- S1: hetero GAT1 (64 -> 256, relu fused) ----
    gat_layer(gat1_W, gat1_al, gat1_ar, gat1_b, t0, w0, t1, w1,
              hs, el, er, alv, arv, rp, col, NT, NW, E);

    // ---- S2: hetero SAGE1 (256 -> 64): project-then-aggregate ----
    {
        wsum_kernel<<<128, 256>>>(sage1_Ws, sage1_b, wsum, bsum);
        // self branches
        gemm1(t1, wsum,         t0, bsum,      NT, 64, 256, 0);
        gemm1(w1, wsum + 16384, w0, bsum + 64, NW, 64, 256, 0);
        // neighbor projections y_r = X_src @ Wn_r  (src of rel r: odd -> t, even -> w)
        gemm1(w1, sage1_Wn + 0 * 16384, hs + 0 * Y64, nullptr, NW, 64, 256, 0);
        gemm1(t1, sage1_Wn + 1 * 16384, hs + 1 * Y64, nullptr, NT, 64, 256, 0);
        gemm1(w1, sage1_Wn + 2 * 16384, hs + 2 * Y64, nullptr, NW, 64, 256, 0);
        gemm1(t1, sage1_Wn + 3 * 16384, hs + 3 * Y64, nullptr, NT, 64, 256, 0);
        // combine with segment means + relu (in place)
        sage1_combine_kernel<<<(NT + 7) / 8, 256>>>(t0, hs + 0 * Y64, hs + 2 * Y64,
                                                    rp0, col0, rp2, col2, NT);
        sage1_combine_kernel<<<(NW + 7) / 8, 256>>>(w0, hs + 1 * Y64, hs + 3 * Y64,
                                                    rp1, col1, rp3, col3, NW);
    }

    // ---- S3: hetero GAT2 (64 -> 256, relu fused) ----
    gat_layer(gat2_W, gat2_al, gat2_ar, gat2_b, t0, w0, t1, w1,
              hs, el, er, alv, arv, rp, col, NT, NW, E);

    // ---- S4: hetero SAGE2 (256 -> 2): project-then-aggregate ----
    {
        const size_t Y2 = (size_t)MAXN * 2;
        float* y0 = el + 0 * Y2;  float* y1 = el + 1 * Y2;
        float* y2 = el + 2 * Y2;  float* y3 = el + 3 * Y2;
        float* selfT = er + 0 * Y2;
        float* selfW = er + 1 * Y2;
        // t-nodes: self uses Ws0+Ws2; t is src of rel 1,3
        proj6_kernel<<<(NT + 7) / 8, 256>>>(t1, sage2_Ws + 0 * 512, sage2_Ws + 2 * 512,
                                            sage2_Wn + 1 * 512, sage2_Wn + 3 * 512,
                                            selfT, y1, y3, NT);
        // w-nodes: self uses Ws1+Ws3; w is src of rel 0,2
        proj6_kernel<<<(NW + 7) / 8, 256>>>(w1, sage2_Ws + 1 * 512, sage2_Ws + 3 * 512,
                                            sage2_Wn + 0 * 512, sage2_Wn + 2 * 512,
                                            selfW, y0, y2, NW);
        sage2_combine_kernel<<<(NT + 255) / 256, 256>>>(fout, selfT, y0, y2,
            rp0, col0, rp2, col2, sage2_b + 0, sage2_b + 4, NT);
        sage2_combine_kernel<<<(NW + 255) / 256, 256>>>(fout + (size_t)NT * 2, selfW, y1, y3,
            rp1, col1, rp3, col3, sage2_b + 2, sage2_b + 6, NW);
    }
}